// round 8
// baseline (speedup 1.0000x reference)
#include <cuda_runtime.h>
#include <cuda_bf16.h>
#include <cstdint>

#define NROWS 16384
#define INF   512
#define HID   256
#define OUTF  16
#define NITER 16
#define SIGMA2 0.1f

// ---------------- scratch (static device globals; no allocation) ----------------
__device__ __nv_bfloat16 g_Lb[(size_t)NROWS * NROWS];          // 512 MB bf16 L
__device__ float         g_h [(size_t)NROWS * HID];            // 16 MB hidden
__device__ float         g_u [2][(size_t)NROWS * OUTF];        // fp32 u ping-pong
__device__ __nv_bfloat16 g_uT[2][(size_t)OUTF * NROWS];        // bf16 u^T ping-pong (B operand)

// ---------------- PTX helpers ----------------
__device__ __forceinline__ uint32_t smem_to_u32(const void* p) {
    uint32_t a;
    asm("{ .reg .u64 t; cvta.to.shared.u64 t, %1; cvt.u32.u64 %0, t; }" : "=r"(a) : "l"(p));
    return a;
}
#define SMEM_SWIZZLE_128B(off) ((off) ^ (((off) >> 3) & 0x70))

__device__ __forceinline__ void cp_async16(uint32_t dst, const void* src) {
    asm volatile("cp.async.cg.shared.global [%0], [%1], 16;" :: "r"(dst), "l"(src) : "memory");
}

#define LDSM_X4(r0_, r1_, r2_, r3_, addr_) \
    asm volatile("ldmatrix.sync.aligned.m8n8.x4.shared.b16 {%0,%1,%2,%3}, [%4];" \
        : "=r"(r0_), "=r"(r1_), "=r"(r2_), "=r"(r3_) : "r"(addr_))

__device__ __forceinline__ void mma16816(float* c, uint32_t a0, uint32_t a1, uint32_t a2,
                                         uint32_t a3, uint32_t b0, uint32_t b1) {
    asm volatile(
        "mma.sync.aligned.m16n8k16.row.col.f32.bf16.bf16.f32 "
        "{%0,%1,%2,%3}, {%4,%5,%6,%7}, {%8,%9}, {%0,%1,%2,%3};"
        : "+f"(c[0]), "+f"(c[1]), "+f"(c[2]), "+f"(c[3])
        : "r"(a0), "r"(a1), "r"(a2), "r"(a3), "r"(b0), "r"(b1));
}

// ---------------- kernel 1: L fp32 -> bf16 (16B stores) ----------------
__global__ void convert_L(const float* __restrict__ L) {
    size_t total8 = (size_t)NROWS * NROWS / 8;
    size_t stride = (size_t)gridDim.x * blockDim.x;
    const float4* L4 = (const float4*)L;
    uint4* out = (uint4*)g_Lb;
    for (size_t i = (size_t)blockIdx.x * blockDim.x + threadIdx.x; i < total8; i += stride) {
        float4 v0 = L4[i * 2];
        float4 v1 = L4[i * 2 + 1];
        __nv_bfloat162 p0 = __floats2bfloat162_rn(v0.x, v0.y);
        __nv_bfloat162 p1 = __floats2bfloat162_rn(v0.z, v0.w);
        __nv_bfloat162 p2 = __floats2bfloat162_rn(v1.x, v1.y);
        __nv_bfloat162 p3 = __floats2bfloat162_rn(v1.z, v1.w);
        uint4 w;
        w.x = *(uint32_t*)&p0; w.y = *(uint32_t*)&p1;
        w.z = *(uint32_t*)&p2; w.w = *(uint32_t*)&p3;
        out[i] = w;
    }
}

// ---------------- kernel 2: h = elu(f @ W1 + b1), fp32 tiled GEMM ----------------
__global__ __launch_bounds__(256) void hidden_kernel(const float* __restrict__ f,
                                                     const float* __restrict__ W1,
                                                     const float* __restrict__ b1) {
    __shared__ float As[16][68];
    __shared__ float Bs[16][68];
    int tx = threadIdx.x, ty = threadIdx.y;
    int tid = ty * 16 + tx;
    int row0 = blockIdx.y * 64;
    int col0 = blockIdx.x * 64;
    float acc[4][4] = {};
    for (int k0 = 0; k0 < INF; k0 += 16) {
        #pragma unroll
        for (int it = 0; it < 4; it++) {
            int r  = (tid >> 4) + it * 16;
            int kk = tid & 15;
            As[kk][r] = f[(size_t)(row0 + r) * INF + k0 + kk];
        }
        #pragma unroll
        for (int it = 0; it < 4; it++) {
            int kk = (tid >> 6) + it * 4;
            int c  = tid & 63;
            Bs[kk][c] = W1[(size_t)(k0 + kk) * HID + col0 + c];
        }
        __syncthreads();
        #pragma unroll
        for (int kk = 0; kk < 16; kk++) {
            float4 a4 = *(const float4*)&As[kk][ty * 4];
            float4 b4 = *(const float4*)&Bs[kk][tx * 4];
            float av[4] = {a4.x, a4.y, a4.z, a4.w};
            float bv[4] = {b4.x, b4.y, b4.z, b4.w};
            #pragma unroll
            for (int i = 0; i < 4; i++)
                #pragma unroll
                for (int j = 0; j < 4; j++)
                    acc[i][j] += av[i] * bv[j];
        }
        __syncthreads();
    }
    #pragma unroll
    for (int i = 0; i < 4; i++) {
        int r = row0 + ty * 4 + i;
        #pragma unroll
        for (int j = 0; j < 4; j++) {
            int c = col0 + tx * 4 + j;
            float v = acc[i][j] + b1[c];
            v = v > 0.0f ? v : expm1f(v);
            g_h[(size_t)r * HID + c] = v;
        }
    }
}

// ---------------- kernel 3: u0 = f@Ws + bs + h@W2 + b2 (also writes bf16 u0^T) ----------------
__global__ __launch_bounds__(256) void u0_kernel(const float* __restrict__ f,
                                                 const float* __restrict__ Ws,
                                                 const float* __restrict__ bs,
                                                 const float* __restrict__ W2,
                                                 const float* __restrict__ b2) {
    __shared__ float sWs[INF * OUTF];   // 32 KB
    __shared__ float sW2[HID * OUTF];   // 16 KB
    int tid = threadIdx.x;
    for (int i = tid; i < INF * OUTF; i += 256) sWs[i] = Ws[i];
    for (int i = tid; i < HID * OUTF; i += 256) sW2[i] = W2[i];
    __syncthreads();
    int c   = tid & 15;
    int row = blockIdx.x * 16 + (tid >> 4);
    float acc = bs[c] + b2[c];
    const float4* f4 = (const float4*)(f + (size_t)row * INF);
    #pragma unroll 4
    for (int k4 = 0; k4 < INF / 4; k4++) {
        float4 v = f4[k4];
        int k = k4 * 4;
        acc += v.x * sWs[k * 16 + c] + v.y * sWs[(k + 1) * 16 + c]
             + v.z * sWs[(k + 2) * 16 + c] + v.w * sWs[(k + 3) * 16 + c];
    }
    const float4* h4 = (const float4*)(g_h + (size_t)row * HID);
    #pragma unroll 4
    for (int k4 = 0; k4 < HID / 4; k4++) {
        float4 v = h4[k4];
        int k = k4 * 4;
        acc += v.x * sW2[k * 16 + c] + v.y * sW2[(k + 1) * 16 + c]
             + v.z * sW2[(k + 2) * 16 + c] + v.w * sW2[(k + 3) * 16 + c];
    }
    g_u[0][(size_t)row * OUTF + c] = acc;
    g_uT[0][(size_t)c * NROWS + row] = __float2bfloat16_rn(acc);
}

// ============================================================================
// diff_kernel: one diffusion step. 256 CTAs x 128 threads (4 warps).
// CTA: D[64,16] = Lb[r0:r0+64,:] @ u ; u_new = u - s2*D.
// KCH=128: each row contributes 256B contiguous per chunk (2 cache lines
// back-to-back) for better DRAM page locality. Stage stores each 256B row as
// two 128B sub-tiles to keep the standard SW128 ldmatrix swizzle.
// NSTG=5 @ 20KB = 100KB smem -> 2 CTAs/SM, all 256 CTAs in one wave.
// ============================================================================
#define KCH 128
#define NCHUNK (NROWS / KCH)           // 128
#define NSTG 5
#define A_SUB 8192                     // 64 rows x 128B
#define B_SUB 2048                     // 16 rows x 128B
#define STG_BYTES (2 * A_SUB + 2 * B_SUB)   // 20480
#define DIFF_SMEM (NSTG * STG_BYTES)        // 102400

__global__ __launch_bounds__(128, 2) void diff_kernel(int sel_in, float* __restrict__ final_out) {
    extern __shared__ char smem[];
    uint32_t sbase = smem_to_u32(smem);
    int tid = threadIdx.x;
    int wid = tid >> 5, lane = tid & 31;
    int r0 = blockIdx.x * 64;

    const __nv_bfloat16* Abase = g_Lb + (size_t)r0 * NROWS;
    const __nv_bfloat16* uT    = g_uT[sel_in];

    // A loads: row = tid>>1 (0..63), sub-tile = tid&1, 8 segs of 16B each.
    const int a_row = tid >> 1;
    const int a_sub = tid & 1;
    // B loads: row = tid>>3 (0..15), seg = tid&7, both sub-tiles.
    const int b_row = tid >> 3;
    const int b_seg = tid & 7;

    auto load_chunk = [&](int j, int s) {
        uint32_t base = sbase + (uint32_t)s * STG_BYTES;
        int k0 = j * KCH;
        const __nv_bfloat16* asrc = Abase + (size_t)a_row * NROWS + k0 + a_sub * 64;
        uint32_t adst = base + (uint32_t)a_sub * A_SUB;
        #pragma unroll
        for (int i = 0; i < 8; i++) {
            uint32_t off = (uint32_t)(a_row * 128 + i * 16);
            cp_async16(adst + SMEM_SWIZZLE_128B(off), asrc + i * 8);
        }
        const __nv_bfloat16* bsrc = uT + (size_t)b_row * NROWS + k0 + b_seg * 8;
        uint32_t boff = SMEM_SWIZZLE_128B((uint32_t)(b_row * 128 + b_seg * 16));
        cp_async16(base + 2 * A_SUB + boff, bsrc);
        cp_async16(base + 2 * A_SUB + B_SUB + boff, bsrc + 64);
    };

    // prologue: chunks 0..NSTG-2
    #pragma unroll
    for (int i = 0; i < NSTG - 1; i++) {
        load_chunk(i, i);
        asm volatile("cp.async.commit_group;" ::: "memory");
    }

    const int a_r = lane & 15;
    const int a_h = (lane >> 4) * 16;
    const int b_n = (lane & 7) + ((lane & 16) ? 8 : 0);
    const int b_h = ((lane >> 3) & 1) * 16;

    float acc0[4] = {0.f, 0.f, 0.f, 0.f};
    float acc1[4] = {0.f, 0.f, 0.f, 0.f};

    for (int i = 0; i < NCHUNK; i++) {
        int s = i % NSTG;
        asm volatile("cp.async.wait_group %0;" :: "n"(NSTG - 2) : "memory");  // chunk i resident
        __syncthreads();   // stage (i-1)%NSTG fully consumed by all warps

        int j = i + NSTG - 1;
        if (j < NCHUNK) load_chunk(j, j % NSTG);   // refill the just-freed stage
        asm volatile("cp.async.commit_group;" ::: "memory");

        uint32_t base = sbase + (uint32_t)s * STG_BYTES;
        #pragma unroll
        for (int sub = 0; sub < 2; sub++) {
            uint32_t Ab = base + (uint32_t)sub * A_SUB;
            uint32_t Bb = base + 2 * A_SUB + (uint32_t)sub * B_SUB;
            #pragma unroll
            for (int kk = 0; kk < 64; kk += 16) {
                uint32_t aoff = (uint32_t)((wid * 16 + a_r) * 128 + kk * 2 + a_h);
                uint32_t a0, a1, a2, a3;
                LDSM_X4(a0, a1, a2, a3, Ab + SMEM_SWIZZLE_128B(aoff));
                uint32_t boff = (uint32_t)(b_n * 128 + kk * 2 + b_h);
                uint32_t b0, b1, b2, b3;
                LDSM_X4(b0, b1, b2, b3, Bb + SMEM_SWIZZLE_128B(boff));
                mma16816(acc0, a0, a1, a2, a3, b0, b1);
                mma16816(acc1, a0, a1, a2, a3, b2, b3);
            }
        }
    }

    // ---- epilogue: u_new = u - sigma2 * D ----
    int gr = lane >> 2;
    int gc = (lane & 3) * 2;
    int rowA = r0 + wid * 16 + gr;
    int rowB = rowA + 8;

    const float* uA = g_u[sel_in] + (size_t)rowA * OUTF;
    const float* uB = g_u[sel_in] + (size_t)rowB * OUTF;
    float rA[4], rB[4];
    rA[0] = uA[gc]     - SIGMA2 * acc0[0];
    rA[1] = uA[gc + 1] - SIGMA2 * acc0[1];
    rA[2] = uA[gc + 8] - SIGMA2 * acc1[0];
    rA[3] = uA[gc + 9] - SIGMA2 * acc1[1];
    rB[0] = uB[gc]     - SIGMA2 * acc0[2];
    rB[1] = uB[gc + 1] - SIGMA2 * acc0[3];
    rB[2] = uB[gc + 8] - SIGMA2 * acc1[2];
    rB[3] = uB[gc + 9] - SIGMA2 * acc1[3];

    if (final_out) {
        *(float2*)(final_out + (size_t)rowA * OUTF + gc)     = make_float2(rA[0], rA[1]);
        *(float2*)(final_out + (size_t)rowA * OUTF + gc + 8) = make_float2(rA[2], rA[3]);
        *(float2*)(final_out + (size_t)rowB * OUTF + gc)     = make_float2(rB[0], rB[1]);
        *(float2*)(final_out + (size_t)rowB * OUTF + gc + 8) = make_float2(rB[2], rB[3]);
    } else {
        int so = sel_in ^ 1;
        float* uo = g_u[so];
        *(float2*)(uo + (size_t)rowA * OUTF + gc)     = make_float2(rA[0], rA[1]);
        *(float2*)(uo + (size_t)rowA * OUTF + gc + 8) = make_float2(rA[2], rA[3]);
        *(float2*)(uo + (size_t)rowB * OUTF + gc)     = make_float2(rB[0], rB[1]);
        *(float2*)(uo + (size_t)rowB * OUTF + gc + 8) = make_float2(rB[2], rB[3]);
        __nv_bfloat16* t = g_uT[so];
        t[(size_t)(gc)     * NROWS + rowA] = __float2bfloat16_rn(rA[0]);
        t[(size_t)(gc + 1) * NROWS + rowA] = __float2bfloat16_rn(rA[1]);
        t[(size_t)(gc + 8) * NROWS + rowA] = __float2bfloat16_rn(rA[2]);
        t[(size_t)(gc + 9) * NROWS + rowA] = __float2bfloat16_rn(rA[3]);
        t[(size_t)(gc)     * NROWS + rowB] = __float2bfloat16_rn(rB[0]);
        t[(size_t)(gc + 1) * NROWS + rowB] = __float2bfloat16_rn(rB[1]);
        t[(size_t)(gc + 8) * NROWS + rowB] = __float2bfloat16_rn(rB[2]);
        t[(size_t)(gc + 9) * NROWS + rowB] = __float2bfloat16_rn(rB[3]);
    }
}

// ---------------- launch ----------------
extern "C" void kernel_launch(void* const* d_in, const int* in_sizes, int n_in,
                              void* d_out, int out_size) {
    const float* f  = (const float*)d_in[0];
    const float* L  = (const float*)d_in[1];
    const float* W1 = (const float*)d_in[2];
    const float* b1 = (const float*)d_in[3];
    const float* W2 = (const float*)d_in[4];
    const float* b2 = (const float*)d_in[5];
    const float* Ws = (const float*)d_in[6];
    const float* bs = (const float*)d_in[7];
    float* out = (float*)d_out;
    (void)in_sizes; (void)n_in; (void)out_size;

    cudaFuncSetAttribute(diff_kernel, cudaFuncAttributeMaxDynamicSharedMemorySize, DIFF_SMEM);

    convert_L<<<8192, 256>>>(L);
    hidden_kernel<<<dim3(HID / 64, NROWS / 64), dim3(16, 16)>>>(f, W1, b1);
    u0_kernel<<<NROWS / 16, 256>>>(f, Ws, bs, W2, b2);

    int sel = 0;
    for (int it = 0; it < NITER; it++) {
        float* fo = (it == NITER - 1) ? out : nullptr;
        diff_kernel<<<NROWS / 64, 128, DIFF_SMEM>>>(sel, fo);
        sel ^= 1;
    }
}

// round 9
// speedup vs baseline: 1.7622x; 1.7622x over previous
#include <cuda_runtime.h>
#include <cuda_bf16.h>
#include <cstdint>

#define NROWS 16384
#define INF   512
#define HID   256
#define OUTF  16
#define NITER 16
#define SIGMA2 0.1f

// ---------------- scratch (static device globals; no allocation) ----------------
__device__ __nv_bfloat16 g_Lb[(size_t)NROWS * NROWS];          // 512 MB bf16 L
__device__ float         g_h [(size_t)NROWS * HID];            // 16 MB hidden
__device__ float         g_u [2][(size_t)NROWS * OUTF];        // fp32 u ping-pong
__device__ __nv_bfloat16 g_uT[2][(size_t)OUTF * NROWS];        // bf16 u^T ping-pong (B operand)

// ---------------- PTX helpers ----------------
__device__ __forceinline__ uint32_t smem_to_u32(const void* p) {
    uint32_t a;
    asm("{ .reg .u64 t; cvta.to.shared.u64 t, %1; cvt.u32.u64 %0, t; }" : "=r"(a) : "l"(p));
    return a;
}
#define SMEM_SWIZZLE_128B(off) ((off) ^ (((off) >> 3) & 0x70))

__device__ __forceinline__ void cp_async16(uint32_t dst, const void* src) {
    asm volatile("cp.async.cg.shared.global [%0], [%1], 16;" :: "r"(dst), "l"(src) : "memory");
}

#define LDSM_X4(r0_, r1_, r2_, r3_, addr_) \
    asm volatile("ldmatrix.sync.aligned.m8n8.x4.shared.b16 {%0,%1,%2,%3}, [%4];" \
        : "=r"(r0_), "=r"(r1_), "=r"(r2_), "=r"(r3_) : "r"(addr_))

__device__ __forceinline__ void mma16816(float* c, uint32_t a0, uint32_t a1, uint32_t a2,
                                         uint32_t a3, uint32_t b0, uint32_t b1) {
    asm volatile(
        "mma.sync.aligned.m16n8k16.row.col.f32.bf16.bf16.f32 "
        "{%0,%1,%2,%3}, {%4,%5,%6,%7}, {%8,%9}, {%0,%1,%2,%3};"
        : "+f"(c[0]), "+f"(c[1]), "+f"(c[2]), "+f"(c[3])
        : "r"(a0), "r"(a1), "r"(a2), "r"(a3), "r"(b0), "r"(b1));
}

// ---------------- kernel 1: L fp32 -> bf16 (16B stores) ----------------
__global__ void convert_L(const float* __restrict__ L) {
    size_t total8 = (size_t)NROWS * NROWS / 8;
    size_t stride = (size_t)gridDim.x * blockDim.x;
    const float4* L4 = (const float4*)L;
    uint4* out = (uint4*)g_Lb;
    for (size_t i = (size_t)blockIdx.x * blockDim.x + threadIdx.x; i < total8; i += stride) {
        float4 v0 = L4[i * 2];
        float4 v1 = L4[i * 2 + 1];
        __nv_bfloat162 p0 = __floats2bfloat162_rn(v0.x, v0.y);
        __nv_bfloat162 p1 = __floats2bfloat162_rn(v0.z, v0.w);
        __nv_bfloat162 p2 = __floats2bfloat162_rn(v1.x, v1.y);
        __nv_bfloat162 p3 = __floats2bfloat162_rn(v1.z, v1.w);
        uint4 w;
        w.x = *(uint32_t*)&p0; w.y = *(uint32_t*)&p1;
        w.z = *(uint32_t*)&p2; w.w = *(uint32_t*)&p3;
        out[i] = w;
    }
}

// ---------------- kernel 2: h = elu(f @ W1 + b1), fp32 tiled GEMM ----------------
__global__ __launch_bounds__(256) void hidden_kernel(const float* __restrict__ f,
                                                     const float* __restrict__ W1,
                                                     const float* __restrict__ b1) {
    __shared__ float As[16][68];
    __shared__ float Bs[16][68];
    int tx = threadIdx.x, ty = threadIdx.y;
    int tid = ty * 16 + tx;
    int row0 = blockIdx.y * 64;
    int col0 = blockIdx.x * 64;
    float acc[4][4] = {};
    for (int k0 = 0; k0 < INF; k0 += 16) {
        #pragma unroll
        for (int it = 0; it < 4; it++) {
            int r  = (tid >> 4) + it * 16;
            int kk = tid & 15;
            As[kk][r] = f[(size_t)(row0 + r) * INF + k0 + kk];
        }
        #pragma unroll
        for (int it = 0; it < 4; it++) {
            int kk = (tid >> 6) + it * 4;
            int c  = tid & 63;
            Bs[kk][c] = W1[(size_t)(k0 + kk) * HID + col0 + c];
        }
        __syncthreads();
        #pragma unroll
        for (int kk = 0; kk < 16; kk++) {
            float4 a4 = *(const float4*)&As[kk][ty * 4];
            float4 b4 = *(const float4*)&Bs[kk][tx * 4];
            float av[4] = {a4.x, a4.y, a4.z, a4.w};
            float bv[4] = {b4.x, b4.y, b4.z, b4.w};
            #pragma unroll
            for (int i = 0; i < 4; i++)
                #pragma unroll
                for (int j = 0; j < 4; j++)
                    acc[i][j] += av[i] * bv[j];
        }
        __syncthreads();
    }
    #pragma unroll
    for (int i = 0; i < 4; i++) {
        int r = row0 + ty * 4 + i;
        #pragma unroll
        for (int j = 0; j < 4; j++) {
            int c = col0 + tx * 4 + j;
            float v = acc[i][j] + b1[c];
            v = v > 0.0f ? v : expm1f(v);
            g_h[(size_t)r * HID + c] = v;
        }
    }
}

// ---------------- kernel 3: u0 = f@Ws + bs + h@W2 + b2 (also writes bf16 u0^T) ----------------
__global__ __launch_bounds__(256) void u0_kernel(const float* __restrict__ f,
                                                 const float* __restrict__ Ws,
                                                 const float* __restrict__ bs,
                                                 const float* __restrict__ W2,
                                                 const float* __restrict__ b2) {
    __shared__ float sWs[INF * OUTF];   // 32 KB
    __shared__ float sW2[HID * OUTF];   // 16 KB
    int tid = threadIdx.x;
    for (int i = tid; i < INF * OUTF; i += 256) sWs[i] = Ws[i];
    for (int i = tid; i < HID * OUTF; i += 256) sW2[i] = W2[i];
    __syncthreads();
    int c   = tid & 15;
    int row = blockIdx.x * 16 + (tid >> 4);
    float acc = bs[c] + b2[c];
    const float4* f4 = (const float4*)(f + (size_t)row * INF);
    #pragma unroll 4
    for (int k4 = 0; k4 < INF / 4; k4++) {
        float4 v = f4[k4];
        int k = k4 * 4;
        acc += v.x * sWs[k * 16 + c] + v.y * sWs[(k + 1) * 16 + c]
             + v.z * sWs[(k + 2) * 16 + c] + v.w * sWs[(k + 3) * 16 + c];
    }
    const float4* h4 = (const float4*)(g_h + (size_t)row * HID);
    #pragma unroll 4
    for (int k4 = 0; k4 < HID / 4; k4++) {
        float4 v = h4[k4];
        int k = k4 * 4;
        acc += v.x * sW2[k * 16 + c] + v.y * sW2[(k + 1) * 16 + c]
             + v.z * sW2[(k + 2) * 16 + c] + v.w * sW2[(k + 3) * 16 + c];
    }
    g_u[0][(size_t)row * OUTF + c] = acc;
    g_uT[0][(size_t)c * NROWS + row] = __float2bfloat16_rn(acc);
}

// ============================================================================
// diff_kernel: one diffusion step. 256 CTAs x 128 threads (4 warps).
// CTA: D[64,16] = Lb[r0:r0+64,:] @ u ; u_new = u - s2*D.
// KCH=128 (256B contiguous per row per chunk) with COALESCED cp.async mapping:
// per instruction, groups of 8 lanes cover one row's 128B contiguously
// (R8's 2-lanes-per-row mapping scattered 32 sectors/instr -> L1tex-bound).
// Row 256B stored as two 128B SW128 sub-tiles. NSTG=5 @ 20KB = 100KB smem,
// 2 CTAs/SM, all 256 CTAs in one wave.
// ============================================================================
#define KCH 128
#define NCHUNK (NROWS / KCH)           // 128
#define NSTG 5
#define A_SUB 8192                     // 64 rows x 128B
#define B_SUB 2048                     // 16 rows x 128B
#define STG_BYTES (2 * A_SUB + 2 * B_SUB)   // 20480
#define DIFF_SMEM (NSTG * STG_BYTES)        // 102400

__global__ __launch_bounds__(128, 2) void diff_kernel(int sel_in, float* __restrict__ final_out) {
    extern __shared__ char smem[];
    uint32_t sbase = smem_to_u32(smem);
    int tid = threadIdx.x;
    int wid = tid >> 5, lane = tid & 31;
    int r0 = blockIdx.x * 64;

    const __nv_bfloat16* Abase = g_Lb + (size_t)r0 * NROWS;
    const __nv_bfloat16* uT    = g_uT[sel_in];

    // Coalesced mapping: 8 lanes per row, 16 rows per instruction.
    const int l_row = tid >> 3;    // 0..15
    const int l_seg = tid & 7;     // 0..7

    auto load_chunk = [&](int j, int s) {
        uint32_t base = sbase + (uint32_t)s * STG_BYTES;
        int k0 = j * KCH;
        #pragma unroll
        for (int i = 0; i < 4; i++) {
            int row = l_row + 16 * i;
            const __nv_bfloat16* src = Abase + (size_t)row * NROWS + k0 + l_seg * 8;
            uint32_t off = SMEM_SWIZZLE_128B((uint32_t)(row * 128 + l_seg * 16));
            cp_async16(base + off, src);              // sub-tile 0: k[0..63]
            cp_async16(base + A_SUB + off, src + 64); // sub-tile 1: k[64..127]
        }
        const __nv_bfloat16* bsrc = uT + (size_t)l_row * NROWS + k0 + l_seg * 8;
        uint32_t boff = SMEM_SWIZZLE_128B((uint32_t)(l_row * 128 + l_seg * 16));
        cp_async16(base + 2 * A_SUB + boff, bsrc);
        cp_async16(base + 2 * A_SUB + B_SUB + boff, bsrc + 64);
    };

    // prologue: chunks 0..NSTG-2
    #pragma unroll
    for (int i = 0; i < NSTG - 1; i++) {
        load_chunk(i, i);
        asm volatile("cp.async.commit_group;" ::: "memory");
    }

    const int a_r = lane & 15;
    const int a_h = (lane >> 4) * 16;
    const int b_n = (lane & 7) + ((lane & 16) ? 8 : 0);
    const int b_h = ((lane >> 3) & 1) * 16;

    float acc0[4] = {0.f, 0.f, 0.f, 0.f};
    float acc1[4] = {0.f, 0.f, 0.f, 0.f};

    for (int i = 0; i < NCHUNK; i++) {
        int s = i % NSTG;
        asm volatile("cp.async.wait_group %0;" :: "n"(NSTG - 2) : "memory");  // chunk i resident
        __syncthreads();   // stage (i-1)%NSTG fully consumed by all warps

        int j = i + NSTG - 1;
        if (j < NCHUNK) load_chunk(j, j % NSTG);   // refill the just-freed stage
        asm volatile("cp.async.commit_group;" ::: "memory");

        uint32_t base = sbase + (uint32_t)s * STG_BYTES;
        #pragma unroll
        for (int sub = 0; sub < 2; sub++) {
            uint32_t Ab = base + (uint32_t)sub * A_SUB;
            uint32_t Bb = base + 2 * A_SUB + (uint32_t)sub * B_SUB;
            #pragma unroll
            for (int kk = 0; kk < 64; kk += 16) {
                uint32_t aoff = (uint32_t)((wid * 16 + a_r) * 128 + kk * 2 + a_h);
                uint32_t a0, a1, a2, a3;
                LDSM_X4(a0, a1, a2, a3, Ab + SMEM_SWIZZLE_128B(aoff));
                uint32_t boff = (uint32_t)(b_n * 128 + kk * 2 + b_h);
                uint32_t b0, b1, b2, b3;
                LDSM_X4(b0, b1, b2, b3, Bb + SMEM_SWIZZLE_128B(boff));
                mma16816(acc0, a0, a1, a2, a3, b0, b1);
                mma16816(acc1, a0, a1, a2, a3, b2, b3);
            }
        }
    }

    // ---- epilogue: u_new = u - sigma2 * D ----
    int gr = lane >> 2;
    int gc = (lane & 3) * 2;
    int rowA = r0 + wid * 16 + gr;
    int rowB = rowA + 8;

    const float* uA = g_u[sel_in] + (size_t)rowA * OUTF;
    const float* uB = g_u[sel_in] + (size_t)rowB * OUTF;
    float rA[4], rB[4];
    rA[0] = uA[gc]     - SIGMA2 * acc0[0];
    rA[1] = uA[gc + 1] - SIGMA2 * acc0[1];
    rA[2] = uA[gc + 8] - SIGMA2 * acc1[0];
    rA[3] = uA[gc + 9] - SIGMA2 * acc1[1];
    rB[0] = uB[gc]     - SIGMA2 * acc0[2];
    rB[1] = uB[gc + 1] - SIGMA2 * acc0[3];
    rB[2] = uB[gc + 8] - SIGMA2 * acc1[2];
    rB[3] = uB[gc + 9] - SIGMA2 * acc1[3];

    if (final_out) {
        *(float2*)(final_out + (size_t)rowA * OUTF + gc)     = make_float2(rA[0], rA[1]);
        *(float2*)(final_out + (size_t)rowA * OUTF + gc + 8) = make_float2(rA[2], rA[3]);
        *(float2*)(final_out + (size_t)rowB * OUTF + gc)     = make_float2(rB[0], rB[1]);
        *(float2*)(final_out + (size_t)rowB * OUTF + gc + 8) = make_float2(rB[2], rB[3]);
    } else {
        int so = sel_in ^ 1;
        float* uo = g_u[so];
        *(float2*)(uo + (size_t)rowA * OUTF + gc)     = make_float2(rA[0], rA[1]);
        *(float2*)(uo + (size_t)rowA * OUTF + gc + 8) = make_float2(rA[2], rA[3]);
        *(float2*)(uo + (size_t)rowB * OUTF + gc)     = make_float2(rB[0], rB[1]);
        *(float2*)(uo + (size_t)rowB * OUTF + gc + 8) = make_float2(rB[2], rB[3]);
        __nv_bfloat16* t = g_uT[so];
        t[(size_t)(gc)     * NROWS + rowA] = __float2bfloat16_rn(rA[0]);
        t[(size_t)(gc + 1) * NROWS + rowA] = __float2bfloat16_rn(rA[1]);
        t[(size_t)(gc + 8) * NROWS + rowA] = __float2bfloat16_rn(rA[2]);
        t[(size_t)(gc + 9) * NROWS + rowA] = __float2bfloat16_rn(rA[3]);
        t[(size_t)(gc)     * NROWS + rowB] = __float2bfloat16_rn(rB[0]);
        t[(size_t)(gc + 1) * NROWS + rowB] = __float2bfloat16_rn(rB[1]);
        t[(size_t)(gc + 8) * NROWS + rowB] = __float2bfloat16_rn(rB[2]);
        t[(size_t)(gc + 9) * NROWS + rowB] = __float2bfloat16_rn(rB[3]);
    }
}

// ---------------- launch ----------------
extern "C" void kernel_launch(void* const* d_in, const int* in_sizes, int n_in,
                              void* d_out, int out_size) {
    const float* f  = (const float*)d_in[0];
    const float* L  = (const float*)d_in[1];
    const float* W1 = (const float*)d_in[2];
    const float* b1 = (const float*)d_in[3];
    const float* W2 = (const float*)d_in[4];
    const float* b2 = (const float*)d_in[5];
    const float* Ws = (const float*)d_in[6];
    const float* bs = (const float*)d_in[7];
    float* out = (float*)d_out;
    (void)in_sizes; (void)n_in; (void)out_size;

    cudaFuncSetAttribute(diff_kernel, cudaFuncAttributeMaxDynamicSharedMemorySize, DIFF_SMEM);

    convert_L<<<8192, 256>>>(L);
    hidden_kernel<<<dim3(HID / 64, NROWS / 64), dim3(16, 16)>>>(f, W1, b1);
    u0_kernel<<<NROWS / 16, 256>>>(f, Ws, bs, W2, b2);

    int sel = 0;
    for (int it = 0; it < NITER; it++) {
        float* fo = (it == NITER - 1) ? out : nullptr;
        diff_kernel<<<NROWS / 64, 128, DIFF_SMEM>>>(sel, fo);
        sel ^= 1;
    }
}

// round 10
// speedup vs baseline: 1.8015x; 1.0223x over previous
#include <cuda_runtime.h>
#include <cuda_bf16.h>
#include <cstdint>

#define NROWS 16384
#define INF   512
#define HID   256
#define OUTF  16
#define NITER 16
#define SIGMA2 0.1f

// ---------------- scratch (static device globals; no allocation) ----------------
__device__ __nv_bfloat16 g_Lb[(size_t)NROWS * NROWS];          // 512 MB bf16 L
__device__ float         g_h [(size_t)NROWS * HID];            // 16 MB hidden
__device__ float         g_u [2][(size_t)NROWS * OUTF];        // fp32 u ping-pong
__device__ __nv_bfloat16 g_uT[2][(size_t)OUTF * NROWS];        // bf16 u^T ping-pong (B operand)

// ---------------- PTX helpers ----------------
__device__ __forceinline__ uint32_t smem_to_u32(const void* p) {
    uint32_t a;
    asm("{ .reg .u64 t; cvta.to.shared.u64 t, %1; cvt.u32.u64 %0, t; }" : "=r"(a) : "l"(p));
    return a;
}
#define SMEM_SWIZZLE_128B(off) ((off) ^ (((off) >> 3) & 0x70))

__device__ __forceinline__ void cp_async16(uint32_t dst, const void* src) {
    asm volatile("cp.async.cg.shared.global [%0], [%1], 16;" :: "r"(dst), "l"(src) : "memory");
}

#define LDSM_X4(r0_, r1_, r2_, r3_, addr_) \
    asm volatile("ldmatrix.sync.aligned.m8n8.x4.shared.b16 {%0,%1,%2,%3}, [%4];" \
        : "=r"(r0_), "=r"(r1_), "=r"(r2_), "=r"(r3_) : "r"(addr_))

__device__ __forceinline__ void mma16816(float* c, uint32_t a0, uint32_t a1, uint32_t a2,
                                         uint32_t a3, uint32_t b0, uint32_t b1) {
    asm volatile(
        "mma.sync.aligned.m16n8k16.row.col.f32.bf16.bf16.f32 "
        "{%0,%1,%2,%3}, {%4,%5,%6,%7}, {%8,%9}, {%0,%1,%2,%3};"
        : "+f"(c[0]), "+f"(c[1]), "+f"(c[2]), "+f"(c[3])
        : "r"(a0), "r"(a1), "r"(a2), "r"(a3), "r"(b0), "r"(b1));
}

// ============================================================================
// prep_kernel: heterogeneous grid fusing two INDEPENDENT jobs so the
// FFMA-bound hidden GEMM hides under the DRAM-bound L conversion stream.
//   blockIdx.x % 3 == 0  (512 blocks): grid-stride fp32->bf16 conversion of L
//   else                 (1024 blocks): one 64x64 tile of h = elu(f@W1 + b1)
// ============================================================================
#define PREP_CONV_BLOCKS 512
#define PREP_HID_BLOCKS  1024          // (HID/64) * (NROWS/64) = 4 * 256
#define PREP_BLOCKS      (PREP_CONV_BLOCKS + PREP_HID_BLOCKS)

__global__ __launch_bounds__(256) void prep_kernel(const float* __restrict__ L,
                                                   const float* __restrict__ f,
                                                   const float* __restrict__ W1,
                                                   const float* __restrict__ b1) {
    __shared__ float As[16][68];
    __shared__ float Bs[16][68];
    int bid = blockIdx.x;

    if (bid % 3 == 0) {
        // ---- conversion slice: L fp32 -> bf16, 16B loads + 16B stores ----
        int conv_id = bid / 3;                       // 0..511
        int tid256 = threadIdx.y * 16 + threadIdx.x; // launched as (16,16)
        size_t total8 = (size_t)NROWS * NROWS / 8;
        size_t stride = (size_t)PREP_CONV_BLOCKS * 256;
        const float4* L4 = (const float4*)L;
        uint4* out = (uint4*)g_Lb;
        for (size_t i = (size_t)conv_id * 256 + tid256; i < total8; i += stride) {
            float4 v0 = L4[i * 2];
            float4 v1 = L4[i * 2 + 1];
            __nv_bfloat162 p0 = __floats2bfloat162_rn(v0.x, v0.y);
            __nv_bfloat162 p1 = __floats2bfloat162_rn(v0.z, v0.w);
            __nv_bfloat162 p2 = __floats2bfloat162_rn(v1.x, v1.y);
            __nv_bfloat162 p3 = __floats2bfloat162_rn(v1.z, v1.w);
            uint4 w;
            w.x = *(uint32_t*)&p0; w.y = *(uint32_t*)&p1;
            w.z = *(uint32_t*)&p2; w.w = *(uint32_t*)&p3;
            out[i] = w;
        }
        return;
    }

    // ---- hidden tile: h[row0:row0+64, col0:col0+64] ----
    int hid_id = bid - bid / 3 - 1;                  // 0..1023 over non-multiples of 3
    int tx = threadIdx.x, ty = threadIdx.y;
    int tid = ty * 16 + tx;
    int col0 = (hid_id & 3) * 64;
    int row0 = (hid_id >> 2) * 64;
    float acc[4][4] = {};
    for (int k0 = 0; k0 < INF; k0 += 16) {
        #pragma unroll
        for (int it = 0; it < 4; it++) {
            int r  = (tid >> 4) + it * 16;
            int kk = tid & 15;
            As[kk][r] = f[(size_t)(row0 + r) * INF + k0 + kk];
        }
        #pragma unroll
        for (int it = 0; it < 4; it++) {
            int kk = (tid >> 6) + it * 4;
            int c  = tid & 63;
            Bs[kk][c] = W1[(size_t)(k0 + kk) * HID + col0 + c];
        }
        __syncthreads();
        #pragma unroll
        for (int kk = 0; kk < 16; kk++) {
            float4 a4 = *(const float4*)&As[kk][ty * 4];
            float4 b4 = *(const float4*)&Bs[kk][tx * 4];
            float av[4] = {a4.x, a4.y, a4.z, a4.w};
            float bv[4] = {b4.x, b4.y, b4.z, b4.w};
            #pragma unroll
            for (int i = 0; i < 4; i++)
                #pragma unroll
                for (int j = 0; j < 4; j++)
                    acc[i][j] += av[i] * bv[j];
        }
        __syncthreads();
    }
    #pragma unroll
    for (int i = 0; i < 4; i++) {
        int r = row0 + ty * 4 + i;
        #pragma unroll
        for (int j = 0; j < 4; j++) {
            int c = col0 + tx * 4 + j;
            float v = acc[i][j] + b1[c];
            v = v > 0.0f ? v : expm1f(v);
            g_h[(size_t)r * HID + c] = v;
        }
    }
}

// ---------------- kernel: u0 = f@Ws + bs + h@W2 + b2 (also writes bf16 u0^T) ----------------
__global__ __launch_bounds__(256) void u0_kernel(const float* __restrict__ f,
                                                 const float* __restrict__ Ws,
                                                 const float* __restrict__ bs,
                                                 const float* __restrict__ W2,
                                                 const float* __restrict__ b2) {
    __shared__ float sWs[INF * OUTF];   // 32 KB
    __shared__ float sW2[HID * OUTF];   // 16 KB
    int tid = threadIdx.x;
    for (int i = tid; i < INF * OUTF; i += 256) sWs[i] = Ws[i];
    for (int i = tid; i < HID * OUTF; i += 256) sW2[i] = W2[i];
    __syncthreads();
    int c   = tid & 15;
    int row = blockIdx.x * 16 + (tid >> 4);
    float acc = bs[c] + b2[c];
    const float4* f4 = (const float4*)(f + (size_t)row * INF);
    #pragma unroll 4
    for (int k4 = 0; k4 < INF / 4; k4++) {
        float4 v = f4[k4];
        int k = k4 * 4;
        acc += v.x * sWs[k * 16 + c] + v.y * sWs[(k + 1) * 16 + c]
             + v.z * sWs[(k + 2) * 16 + c] + v.w * sWs[(k + 3) * 16 + c];
    }
    const float4* h4 = (const float4*)(g_h + (size_t)row * HID);
    #pragma unroll 4
    for (int k4 = 0; k4 < HID / 4; k4++) {
        float4 v = h4[k4];
        int k = k4 * 4;
        acc += v.x * sW2[k * 16 + c] + v.y * sW2[(k + 1) * 16 + c]
             + v.z * sW2[(k + 2) * 16 + c] + v.w * sW2[(k + 3) * 16 + c];
    }
    g_u[0][(size_t)row * OUTF + c] = acc;
    g_uT[0][(size_t)c * NROWS + row] = __float2bfloat16_rn(acc);
}

// ============================================================================
// diff_kernel: one diffusion step. 256 CTAs x 128 threads (4 warps).
// CTA: D[64,16] = Lb[r0:r0+64,:] @ u ; u_new = u - s2*D.
// KCH=128 (256B contiguous per row per chunk), coalesced cp.async mapping
// (8 lanes cover one row's 128B per instruction). Row 256B stored as two
// 128B SW128 sub-tiles. NSTG=5 @ 20KB = 100KB smem, 2 CTAs/SM, one wave.
// ============================================================================
#define KCH 128
#define NCHUNK (NROWS / KCH)           // 128
#define NSTG 5
#define A_SUB 8192                     // 64 rows x 128B
#define B_SUB 2048                     // 16 rows x 128B
#define STG_BYTES (2 * A_SUB + 2 * B_SUB)   // 20480
#define DIFF_SMEM (NSTG * STG_BYTES)        // 102400

__global__ __launch_bounds__(128, 2) void diff_kernel(int sel_in, float* __restrict__ final_out) {
    extern __shared__ char smem[];
    uint32_t sbase = smem_to_u32(smem);
    int tid = threadIdx.x;
    int wid = tid >> 5, lane = tid & 31;
    int r0 = blockIdx.x * 64;

    const __nv_bfloat16* Abase = g_Lb + (size_t)r0 * NROWS;
    const __nv_bfloat16* uT    = g_uT[sel_in];

    // Coalesced mapping: 8 lanes per row, 16 rows per instruction.
    const int l_row = tid >> 3;    // 0..15
    const int l_seg = tid & 7;     // 0..7

    auto load_chunk = [&](int j, int s) {
        uint32_t base = sbase + (uint32_t)s * STG_BYTES;
        int k0 = j * KCH;
        #pragma unroll
        for (int i = 0; i < 4; i++) {
            int row = l_row + 16 * i;
            const __nv_bfloat16* src = Abase + (size_t)row * NROWS + k0 + l_seg * 8;
            uint32_t off = SMEM_SWIZZLE_128B((uint32_t)(row * 128 + l_seg * 16));
            cp_async16(base + off, src);              // sub-tile 0: k[0..63]
            cp_async16(base + A_SUB + off, src + 64); // sub-tile 1: k[64..127]
        }
        const __nv_bfloat16* bsrc = uT + (size_t)l_row * NROWS + k0 + l_seg * 8;
        uint32_t boff = SMEM_SWIZZLE_128B((uint32_t)(l_row * 128 + l_seg * 16));
        cp_async16(base + 2 * A_SUB + boff, bsrc);
        cp_async16(base + 2 * A_SUB + B_SUB + boff, bsrc + 64);
    };

    // prologue: chunks 0..NSTG-2
    #pragma unroll
    for (int i = 0; i < NSTG - 1; i++) {
        load_chunk(i, i);
        asm volatile("cp.async.commit_group;" ::: "memory");
    }

    const int a_r = lane & 15;
    const int a_h = (lane >> 4) * 16;
    const int b_n = (lane & 7) + ((lane & 16) ? 8 : 0);
    const int b_h = ((lane >> 3) & 1) * 16;

    float acc0[4] = {0.f, 0.f, 0.f, 0.f};
    float acc1[4] = {0.f, 0.f, 0.f, 0.f};

    for (int i = 0; i < NCHUNK; i++) {
        int s = i % NSTG;
        asm volatile("cp.async.wait_group %0;" :: "n"(NSTG - 2) : "memory");  // chunk i resident
        __syncthreads();   // stage (i-1)%NSTG fully consumed by all warps

        int j = i + NSTG - 1;
        if (j < NCHUNK) load_chunk(j, j % NSTG);   // refill the just-freed stage
        asm volatile("cp.async.commit_group;" ::: "memory");

        uint32_t base = sbase + (uint32_t)s * STG_BYTES;
        #pragma unroll
        for (int sub = 0; sub < 2; sub++) {
            uint32_t Ab = base + (uint32_t)sub * A_SUB;
            uint32_t Bb = base + 2 * A_SUB + (uint32_t)sub * B_SUB;
            #pragma unroll
            for (int kk = 0; kk < 64; kk += 16) {
                uint32_t aoff = (uint32_t)((wid * 16 + a_r) * 128 + kk * 2 + a_h);
                uint32_t a0, a1, a2, a3;
                LDSM_X4(a0, a1, a2, a3, Ab + SMEM_SWIZZLE_128B(aoff));
                uint32_t boff = (uint32_t)(b_n * 128 + kk * 2 + b_h);
                uint32_t b0, b1, b2, b3;
                LDSM_X4(b0, b1, b2, b3, Bb + SMEM_SWIZZLE_128B(boff));
                mma16816(acc0, a0, a1, a2, a3, b0, b1);
                mma16816(acc1, a0, a1, a2, a3, b2, b3);
            }
        }
    }

    // ---- epilogue: u_new = u - sigma2 * D ----
    int gr = lane >> 2;
    int gc = (lane & 3) * 2;
    int rowA = r0 + wid * 16 + gr;
    int rowB = rowA + 8;

    const float* uA = g_u[sel_in] + (size_t)rowA * OUTF;
    const float* uB = g_u[sel_in] + (size_t)rowB * OUTF;
    float rA[4], rB[4];
    rA[0] = uA[gc]     - SIGMA2 * acc0[0];
    rA[1] = uA[gc + 1] - SIGMA2 * acc0[1];
    rA[2] = uA[gc + 8] - SIGMA2 * acc1[0];
    rA[3] = uA[gc + 9] - SIGMA2 * acc1[1];
    rB[0] = uB[gc]     - SIGMA2 * acc0[2];
    rB[1] = uB[gc + 1] - SIGMA2 * acc0[3];
    rB[2] = uB[gc + 8] - SIGMA2 * acc1[2];
    rB[3] = uB[gc + 9] - SIGMA2 * acc1[3];

    if (final_out) {
        *(float2*)(final_out + (size_t)rowA * OUTF + gc)     = make_float2(rA[0], rA[1]);
        *(float2*)(final_out + (size_t)rowA * OUTF + gc + 8) = make_float2(rA[2], rA[3]);
        *(float2*)(final_out + (size_t)rowB * OUTF + gc)     = make_float2(rB[0], rB[1]);
        *(float2*)(final_out + (size_t)rowB * OUTF + gc + 8) = make_float2(rB[2], rB[3]);
    } else {
        int so = sel_in ^ 1;
        float* uo = g_u[so];
        *(float2*)(uo + (size_t)rowA * OUTF + gc)     = make_float2(rA[0], rA[1]);
        *(float2*)(uo + (size_t)rowA * OUTF + gc + 8) = make_float2(rA[2], rA[3]);
        *(float2*)(uo + (size_t)rowB * OUTF + gc)     = make_float2(rB[0], rB[1]);
        *(float2*)(uo + (size_t)rowB * OUTF + gc + 8) = make_float2(rB[2], rB[3]);
        __nv_bfloat16* t = g_uT[so];
        t[(size_t)(gc)     * NROWS + rowA] = __float2bfloat16_rn(rA[0]);
        t[(size_t)(gc + 1) * NROWS + rowA] = __float2bfloat16_rn(rA[1]);
        t[(size_t)(gc + 8) * NROWS + rowA] = __float2bfloat16_rn(rA[2]);
        t[(size_t)(gc + 9) * NROWS + rowA] = __float2bfloat16_rn(rA[3]);
        t[(size_t)(gc)     * NROWS + rowB] = __float2bfloat16_rn(rB[0]);
        t[(size_t)(gc + 1) * NROWS + rowB] = __float2bfloat16_rn(rB[1]);
        t[(size_t)(gc + 8) * NROWS + rowB] = __float2bfloat16_rn(rB[2]);
        t[(size_t)(gc + 9) * NROWS + rowB] = __float2bfloat16_rn(rB[3]);
    }
}

// ---------------- launch ----------------
extern "C" void kernel_launch(void* const* d_in, const int* in_sizes, int n_in,
                              void* d_out, int out_size) {
    const float* f  = (const float*)d_in[0];
    const float* L  = (const float*)d_in[1];
    const float* W1 = (const float*)d_in[2];
    const float* b1 = (const float*)d_in[3];
    const float* W2 = (const float*)d_in[4];
    const float* b2 = (const float*)d_in[5];
    const float* Ws = (const float*)d_in[6];
    const float* bs = (const float*)d_in[7];
    float* out = (float*)d_out;
    (void)in_sizes; (void)n_in; (void)out_size;

    cudaFuncSetAttribute(diff_kernel, cudaFuncAttributeMaxDynamicSharedMemorySize, DIFF_SMEM);

    // fused: L conversion (DRAM-bound) + hidden GEMM (FFMA-bound) overlap
    prep_kernel<<<PREP_BLOCKS, dim3(16, 16)>>>(L, f, W1, b1);
    u0_kernel<<<NROWS / 16, 256>>>(f, Ws, bs, W2, b2);

    int sel = 0;
    for (int it = 0; it < NITER; it++) {
        float* fo = (it == NITER - 1) ? out : nullptr;
        diff_kernel<<<NROWS / 64, 128, DIFF_SMEM>>>(sel, fo);
        sel ^= 1;
    }
}

// round 12
// speedup vs baseline: 2.5070x; 1.3916x over previous
#include <cuda_runtime.h>
#include <cuda_bf16.h>
#include <cstdint>

#define NROWS 16384
#define INF   512
#define HID   256
#define OUTF  16
#define NITER 16
#define NFP8  12                       // first 12 steps in fp8, last 4 in bf16
#define SIGMA2 0.1f
#define L8_SCALE 8192.0f               // L stored as L * 2^13 in e4m3

// ---------------- scratch (static device globals; no allocation) ----------------
__device__ __nv_bfloat16 g_Lb[(size_t)NROWS * NROWS];          // 512 MB bf16 L
__device__ unsigned char g_L8[(size_t)NROWS * NROWS];          // 256 MB e4m3 L * 2^13
__device__ float         g_h [(size_t)NROWS * HID];            // 16 MB hidden
__device__ float         g_u [2][(size_t)NROWS * OUTF];        // fp32 u ping-pong
__device__ __nv_bfloat16 g_uT[2][(size_t)OUTF * NROWS];        // bf16 u^T ping-pong
__device__ unsigned char g_uT8[2][(size_t)OUTF * NROWS];       // e4m3 u^T ping-pong

// ---------------- PTX helpers ----------------
__device__ __forceinline__ uint32_t smem_to_u32(const void* p) {
    uint32_t a;
    asm("{ .reg .u64 t; cvta.to.shared.u64 t, %1; cvt.u32.u64 %0, t; }" : "=r"(a) : "l"(p));
    return a;
}
#define SMEM_SWIZZLE_128B(off) ((off) ^ (((off) >> 3) & 0x70))

__device__ __forceinline__ void cp_async16(uint32_t dst, const void* src) {
    asm volatile("cp.async.cg.shared.global [%0], [%1], 16;" :: "r"(dst), "l"(src) : "memory");
}

#define LDSM_X4(r0_, r1_, r2_, r3_, addr_) \
    asm volatile("ldmatrix.sync.aligned.m8n8.x4.shared.b16 {%0,%1,%2,%3}, [%4];" \
        : "=r"(r0_), "=r"(r1_), "=r"(r2_), "=r"(r3_) : "r"(addr_))

__device__ __forceinline__ void mma16816(float* c, uint32_t a0, uint32_t a1, uint32_t a2,
                                         uint32_t a3, uint32_t b0, uint32_t b1) {
    asm volatile(
        "mma.sync.aligned.m16n8k16.row.col.f32.bf16.bf16.f32 "
        "{%0,%1,%2,%3}, {%4,%5,%6,%7}, {%8,%9}, {%0,%1,%2,%3};"
        : "+f"(c[0]), "+f"(c[1]), "+f"(c[2]), "+f"(c[3])
        : "r"(a0), "r"(a1), "r"(a2), "r"(a3), "r"(b0), "r"(b1));
}

__device__ __forceinline__ void mma16832_e4m3(float* c, uint32_t a0, uint32_t a1, uint32_t a2,
                                              uint32_t a3, uint32_t b0, uint32_t b1) {
    asm volatile(
        "mma.sync.aligned.m16n8k32.row.col.f32.e4m3.e4m3.f32 "
        "{%0,%1,%2,%3}, {%4,%5,%6,%7}, {%8,%9}, {%0,%1,%2,%3};"
        : "+f"(c[0]), "+f"(c[1]), "+f"(c[2]), "+f"(c[3])
        : "r"(a0), "r"(a1), "r"(a2), "r"(a3), "r"(b0), "r"(b1));
}

// pack two floats -> two e4m3 bytes (lo = x, hi = y)
__device__ __forceinline__ uint16_t f2_to_e4m3x2(float x, float y) {
    uint16_t p;
    asm("cvt.rn.satfinite.e4m3x2.f32 %0, %1, %2;" : "=h"(p) : "f"(y), "f"(x));
    return p;
}
__device__ __forceinline__ unsigned char f_to_e4m3(float v) {
    return (unsigned char)(f2_to_e4m3x2(v, 0.f) & 0xFF);
}

// ============================================================================
// prep_kernel: heterogeneous grid fusing two INDEPENDENT jobs.
//   blockIdx.x % 3 == 0  (512 blocks): L fp32 -> {bf16, e4m3*2^13}
//   else                 (1024 blocks): one 64x64 tile of h = elu(f@W1 + b1)
// ============================================================================
#define PREP_CONV_BLOCKS 512
#define PREP_HID_BLOCKS  1024
#define PREP_BLOCKS      (PREP_CONV_BLOCKS + PREP_HID_BLOCKS)

__global__ __launch_bounds__(256) void prep_kernel(const float* __restrict__ L,
                                                   const float* __restrict__ f,
                                                   const float* __restrict__ W1,
                                                   const float* __restrict__ b1) {
    __shared__ float As[16][68];
    __shared__ float Bs[16][68];
    int bid = blockIdx.x;

    if (bid % 3 == 0) {
        int conv_id = bid / 3;
        int tid256 = threadIdx.y * 16 + threadIdx.x;
        size_t total8 = (size_t)NROWS * NROWS / 8;
        size_t stride = (size_t)PREP_CONV_BLOCKS * 256;
        const float4* L4 = (const float4*)L;
        uint4* out16 = (uint4*)g_Lb;
        uint2* out8  = (uint2*)g_L8;
        for (size_t i = (size_t)conv_id * 256 + tid256; i < total8; i += stride) {
            float4 v0 = L4[i * 2];
            float4 v1 = L4[i * 2 + 1];
            __nv_bfloat162 p0 = __floats2bfloat162_rn(v0.x, v0.y);
            __nv_bfloat162 p1 = __floats2bfloat162_rn(v0.z, v0.w);
            __nv_bfloat162 p2 = __floats2bfloat162_rn(v1.x, v1.y);
            __nv_bfloat162 p3 = __floats2bfloat162_rn(v1.z, v1.w);
            uint4 w;
            w.x = *(uint32_t*)&p0; w.y = *(uint32_t*)&p1;
            w.z = *(uint32_t*)&p2; w.w = *(uint32_t*)&p3;
            out16[i] = w;
            uint32_t q01 = f2_to_e4m3x2(v0.x * L8_SCALE, v0.y * L8_SCALE)
                         | ((uint32_t)f2_to_e4m3x2(v0.z * L8_SCALE, v0.w * L8_SCALE) << 16);
            uint32_t q23 = f2_to_e4m3x2(v1.x * L8_SCALE, v1.y * L8_SCALE)
                         | ((uint32_t)f2_to_e4m3x2(v1.z * L8_SCALE, v1.w * L8_SCALE) << 16);
            out8[i] = make_uint2(q01, q23);
        }
        return;
    }

    int hid_id = bid - bid / 3 - 1;
    int tx = threadIdx.x, ty = threadIdx.y;
    int tid = ty * 16 + tx;
    int col0 = (hid_id & 3) * 64;
    int row0 = (hid_id >> 2) * 64;
    float acc[4][4] = {};
    for (int k0 = 0; k0 < INF; k0 += 16) {
        #pragma unroll
        for (int it = 0; it < 4; it++) {
            int r  = (tid >> 4) + it * 16;
            int kk = tid & 15;
            As[kk][r] = f[(size_t)(row0 + r) * INF + k0 + kk];
        }
        #pragma unroll
        for (int it = 0; it < 4; it++) {
            int kk = (tid >> 6) + it * 4;
            int c  = tid & 63;
            Bs[kk][c] = W1[(size_t)(k0 + kk) * HID + col0 + c];
        }
        __syncthreads();
        #pragma unroll
        for (int kk = 0; kk < 16; kk++) {
            float4 a4 = *(const float4*)&As[kk][ty * 4];
            float4 b4 = *(const float4*)&Bs[kk][tx * 4];
            float av[4] = {a4.x, a4.y, a4.z, a4.w};
            float bv[4] = {b4.x, b4.y, b4.z, b4.w};
            #pragma unroll
            for (int i = 0; i < 4; i++)
                #pragma unroll
                for (int j = 0; j < 4; j++)
                    acc[i][j] += av[i] * bv[j];
        }
        __syncthreads();
    }
    #pragma unroll
    for (int i = 0; i < 4; i++) {
        int r = row0 + ty * 4 + i;
        #pragma unroll
        for (int j = 0; j < 4; j++) {
            int c = col0 + tx * 4 + j;
            float v = acc[i][j] + b1[c];
            v = v > 0.0f ? v : expm1f(v);
            g_h[(size_t)r * HID + c] = v;
        }
    }
}

// ---------------- u0 = f@Ws + bs + h@W2 + b2 (writes bf16 + fp8 u0^T) ----------------
__global__ __launch_bounds__(256) void u0_kernel(const float* __restrict__ f,
                                                 const float* __restrict__ Ws,
                                                 const float* __restrict__ bs,
                                                 const float* __restrict__ W2,
                                                 const float* __restrict__ b2) {
    __shared__ float sWs[INF * OUTF];
    __shared__ float sW2[HID * OUTF];
    int tid = threadIdx.x;
    for (int i = tid; i < INF * OUTF; i += 256) sWs[i] = Ws[i];
    for (int i = tid; i < HID * OUTF; i += 256) sW2[i] = W2[i];
    __syncthreads();
    int c   = tid & 15;
    int row = blockIdx.x * 16 + (tid >> 4);
    float acc = bs[c] + b2[c];
    const float4* f4 = (const float4*)(f + (size_t)row * INF);
    #pragma unroll 4
    for (int k4 = 0; k4 < INF / 4; k4++) {
        float4 v = f4[k4];
        int k = k4 * 4;
        acc += v.x * sWs[k * 16 + c] + v.y * sWs[(k + 1) * 16 + c]
             + v.z * sWs[(k + 2) * 16 + c] + v.w * sWs[(k + 3) * 16 + c];
    }
    const float4* h4 = (const float4*)(g_h + (size_t)row * HID);
    #pragma unroll 4
    for (int k4 = 0; k4 < HID / 4; k4++) {
        float4 v = h4[k4];
        int k = k4 * 4;
        acc += v.x * sW2[k * 16 + c] + v.y * sW2[(k + 1) * 16 + c]
             + v.z * sW2[(k + 2) * 16 + c] + v.w * sW2[(k + 3) * 16 + c];
    }
    g_u[0][(size_t)row * OUTF + c] = acc;
    g_uT[0][(size_t)c * NROWS + row] = __float2bfloat16_rn(acc);
    g_uT8[0][(size_t)c * NROWS + row] = f_to_e4m3(acc);
}

// ============================================================================
// Shared epilogue: u_new = u - scale * D ; writes fp32 u (or d_out) + both u^T
// ============================================================================
__device__ __forceinline__ void diff_epilogue(int sel_in, float* final_out, float s2,
                                              int r0, int wid, int lane,
                                              const float* acc0, const float* acc1) {
    int gr = lane >> 2;
    int gc = (lane & 3) * 2;
    int rowA = r0 + wid * 16 + gr;
    int rowB = rowA + 8;

    const float* uA = g_u[sel_in] + (size_t)rowA * OUTF;
    const float* uB = g_u[sel_in] + (size_t)rowB * OUTF;
    float rA[4], rB[4];
    rA[0] = uA[gc]     - s2 * acc0[0];
    rA[1] = uA[gc + 1] - s2 * acc0[1];
    rA[2] = uA[gc + 8] - s2 * acc1[0];
    rA[3] = uA[gc + 9] - s2 * acc1[1];
    rB[0] = uB[gc]     - s2 * acc0[2];
    rB[1] = uB[gc + 1] - s2 * acc0[3];
    rB[2] = uB[gc + 8] - s2 * acc1[2];
    rB[3] = uB[gc + 9] - s2 * acc1[3];

    if (final_out) {
        *(float2*)(final_out + (size_t)rowA * OUTF + gc)     = make_float2(rA[0], rA[1]);
        *(float2*)(final_out + (size_t)rowA * OUTF + gc + 8) = make_float2(rA[2], rA[3]);
        *(float2*)(final_out + (size_t)rowB * OUTF + gc)     = make_float2(rB[0], rB[1]);
        *(float2*)(final_out + (size_t)rowB * OUTF + gc + 8) = make_float2(rB[2], rB[3]);
    } else {
        int so = sel_in ^ 1;
        float* uo = g_u[so];
        *(float2*)(uo + (size_t)rowA * OUTF + gc)     = make_float2(rA[0], rA[1]);
        *(float2*)(uo + (size_t)rowA * OUTF + gc + 8) = make_float2(rA[2], rA[3]);
        *(float2*)(uo + (size_t)rowB * OUTF + gc)     = make_float2(rB[0], rB[1]);
        *(float2*)(uo + (size_t)rowB * OUTF + gc + 8) = make_float2(rB[2], rB[3]);
        __nv_bfloat16* t = g_uT[so];
        unsigned char* t8 = g_uT8[so];
        #pragma unroll
        for (int q = 0; q < 4; q++) {
            int cA = (q < 2) ? gc + q : gc + 6 + q;   // gc,gc+1,gc+8,gc+9
            t[(size_t)cA * NROWS + rowA] = __float2bfloat16_rn(rA[q]);
            t[(size_t)cA * NROWS + rowB] = __float2bfloat16_rn(rB[q]);
            t8[(size_t)cA * NROWS + rowA] = f_to_e4m3(rA[q]);
            t8[(size_t)cA * NROWS + rowB] = f_to_e4m3(rB[q]);
        }
    }
}

// ---- shared pipeline geometry (both diff kernels) ----
#define NSTG 5
#define A_SUB 8192                     // 64 rows x 128B
#define B_SUB 2048                     // 16 rows x 128B
#define STG_BYTES (2 * A_SUB + 2 * B_SUB)   // 20480
#define DIFF_SMEM (NSTG * STG_BYTES)        // 102400

// ============================================================================
// diff_kernel (bf16): KCH=128 elements (256B/row/chunk), NCHUNK=128.
// ============================================================================
#define KCH16 128
#define NCHUNK16 (NROWS / KCH16)       // 128

__global__ __launch_bounds__(128, 2) void diff_kernel(int sel_in, float* __restrict__ final_out) {
    extern __shared__ char smem[];
    uint32_t sbase = smem_to_u32(smem);
    int tid = threadIdx.x;
    int wid = tid >> 5, lane = tid & 31;
    int r0 = blockIdx.x * 64;

    const __nv_bfloat16* Abase = g_Lb + (size_t)r0 * NROWS;
    const __nv_bfloat16* uT    = g_uT[sel_in];

    const int l_row = tid >> 3;
    const int l_seg = tid & 7;

    auto load_chunk = [&](int j, int s) {
        uint32_t base = sbase + (uint32_t)s * STG_BYTES;
        int k0 = j * KCH16;
        #pragma unroll
        for (int i = 0; i < 4; i++) {
            int row = l_row + 16 * i;
            const __nv_bfloat16* src = Abase + (size_t)row * NROWS + k0 + l_seg * 8;
            uint32_t off = SMEM_SWIZZLE_128B((uint32_t)(row * 128 + l_seg * 16));
            cp_async16(base + off, src);
            cp_async16(base + A_SUB + off, src + 64);
        }
        const __nv_bfloat16* bsrc = uT + (size_t)l_row * NROWS + k0 + l_seg * 8;
        uint32_t boff = SMEM_SWIZZLE_128B((uint32_t)(l_row * 128 + l_seg * 16));
        cp_async16(base + 2 * A_SUB + boff, bsrc);
        cp_async16(base + 2 * A_SUB + B_SUB + boff, bsrc + 64);
    };

    #pragma unroll
    for (int i = 0; i < NSTG - 1; i++) {
        load_chunk(i, i);
        asm volatile("cp.async.commit_group;" ::: "memory");
    }

    const int a_r = lane & 15;
    const int a_h = (lane >> 4) * 16;
    const int b_n = (lane & 7) + ((lane & 16) ? 8 : 0);
    const int b_h = ((lane >> 3) & 1) * 16;

    float acc0[4] = {0.f, 0.f, 0.f, 0.f};
    float acc1[4] = {0.f, 0.f, 0.f, 0.f};

    for (int i = 0; i < NCHUNK16; i++) {
        int s = i % NSTG;
        asm volatile("cp.async.wait_group %0;" :: "n"(NSTG - 2) : "memory");
        __syncthreads();

        int j = i + NSTG - 1;
        if (j < NCHUNK16) load_chunk(j, j % NSTG);
        asm volatile("cp.async.commit_group;" ::: "memory");

        uint32_t base = sbase + (uint32_t)s * STG_BYTES;
        #pragma unroll
        for (int sub = 0; sub < 2; sub++) {
            uint32_t Ab = base + (uint32_t)sub * A_SUB;
            uint32_t Bb = base + 2 * A_SUB + (uint32_t)sub * B_SUB;
            #pragma unroll
            for (int kk = 0; kk < 64; kk += 16) {
                uint32_t aoff = (uint32_t)((wid * 16 + a_r) * 128 + kk * 2 + a_h);
                uint32_t a0, a1, a2, a3;
                LDSM_X4(a0, a1, a2, a3, Ab + SMEM_SWIZZLE_128B(aoff));
                uint32_t boff = (uint32_t)(b_n * 128 + kk * 2 + b_h);
                uint32_t b0, b1, b2, b3;
                LDSM_X4(b0, b1, b2, b3, Bb + SMEM_SWIZZLE_128B(boff));
                mma16816(acc0, a0, a1, a2, a3, b0, b1);
                mma16816(acc1, a0, a1, a2, a3, b2, b3);
            }
        }
    }

    diff_epilogue(sel_in, final_out, SIGMA2, r0, wid, lane, acc0, acc1);
}

// ============================================================================
// diff8_kernel (e4m3): byte-identical smem layout (each 16-bit lane = 2 fp8).
// KCH=256 elements = 256B/row/chunk, NCHUNK=64. Same stages/pipeline.
// ============================================================================
#define KCH8 256
#define NCHUNK8 (NROWS / KCH8)         // 64

__global__ __launch_bounds__(128, 2) void diff8_kernel(int sel_in, float* __restrict__ final_out) {
    extern __shared__ char smem[];
    uint32_t sbase = smem_to_u32(smem);
    int tid = threadIdx.x;
    int wid = tid >> 5, lane = tid & 31;
    int r0 = blockIdx.x * 64;

    const unsigned char* Abase = g_L8 + (size_t)r0 * NROWS;
    const unsigned char* uT    = g_uT8[sel_in];

    const int l_row = tid >> 3;
    const int l_seg = tid & 7;

    auto load_chunk = [&](int j, int s) {
        uint32_t base = sbase + (uint32_t)s * STG_BYTES;
        int k0 = j * KCH8;   // bytes
        #pragma unroll
        for (int i = 0; i < 4; i++) {
            int row = l_row + 16 * i;
            const unsigned char* src = Abase + (size_t)row * NROWS + k0 + l_seg * 16;
            uint32_t off = SMEM_SWIZZLE_128B((uint32_t)(row * 128 + l_seg * 16));
            cp_async16(base + off, src);               // sub-tile 0: k[0..127]
            cp_async16(base + A_SUB + off, src + 128); // sub-tile 1: k[128..255]
        }
        const unsigned char* bsrc = uT + (size_t)l_row * NROWS + k0 + l_seg * 16;
        uint32_t boff = SMEM_SWIZZLE_128B((uint32_t)(l_row * 128 + l_seg * 16));
        cp_async16(base + 2 * A_SUB + boff, bsrc);
        cp_async16(base + 2 * A_SUB + B_SUB + boff, bsrc + 128);
    };

    #pragma unroll
    for (int i = 0; i < NSTG - 1; i++) {
        load_chunk(i, i);
        asm volatile("cp.async.commit_group;" ::: "memory");
    }

    const int a_r = lane & 15;
    const int a_h = (lane >> 4) * 16;
    const int b_n = (lane & 7) + ((lane & 16) ? 8 : 0);
    const int b_h = ((lane >> 3) & 1) * 16;

    float acc0[4] = {0.f, 0.f, 0.f, 0.f};
    float acc1[4] = {0.f, 0.f, 0.f, 0.f};

    for (int i = 0; i < NCHUNK8; i++) {
        int s = i % NSTG;
        asm volatile("cp.async.wait_group %0;" :: "n"(NSTG - 2) : "memory");
        __syncthreads();

        int j = i + NSTG - 1;
        if (j < NCHUNK8) load_chunk(j, j % NSTG);
        asm volatile("cp.async.commit_group;" ::: "memory");

        uint32_t base = sbase + (uint32_t)s * STG_BYTES;
        #pragma unroll
        for (int sub = 0; sub < 2; sub++) {
            uint32_t Ab = base + (uint32_t)sub * A_SUB;
            uint32_t Bb = base + 2 * A_SUB + (uint32_t)sub * B_SUB;
            #pragma unroll
            for (int kk = 0; kk < 64; kk += 16) {     // pseudo-b16 units; 32 real k each
                uint32_t aoff = (uint32_t)((wid * 16 + a_r) * 128 + kk * 2 + a_h);
                uint32_t a0, a1, a2, a3;
                LDSM_X4(a0, a1, a2, a3, Ab + SMEM_SWIZZLE_128B(aoff));
                uint32_t boff = (uint32_t)(b_n * 128 + kk * 2 + b_h);
                uint32_t b0, b1, b2, b3;
                LDSM_X4(b0, b1, b2, b3, Bb + SMEM_SWIZZLE_128B(boff));
                mma16832_e4m3(acc0, a0, a1, a2, a3, b0, b1);
                mma16832_e4m3(acc1, a0, a1, a2, a3, b2, b3);
            }
        }
    }

    // acc = (L*2^13) @ u  ->  scale sigma2 by 2^-13
    diff_epilogue(sel_in, final_out, SIGMA2 / L8_SCALE, r0, wid, lane, acc0, acc1);
}

// ---------------- launch ----------------
extern "C" void kernel_launch(void* const* d_in, const int* in_sizes, int n_in,
                              void* d_out, int out_size) {
    const float* f  = (const float*)d_in[0];
    const float* L  = (const float*)d_in[1];
    const float* W1 = (const float*)d_in[2];
    const float* b1 = (const float*)d_in[3];
    const float* W2 = (const float*)d_in[4];
    const float* b2 = (const float*)d_in[5];
    const float* Ws = (const float*)d_in[6];
    const float* bs = (const float*)d_in[7];
    float* out = (float*)d_out;
    (void)in_sizes; (void)n_in; (void)out_size;

    cudaFuncSetAttribute(diff_kernel,  cudaFuncAttributeMaxDynamicSharedMemorySize, DIFF_SMEM);
    cudaFuncSetAttribute(diff8_kernel, cudaFuncAttributeMaxDynamicSharedMemorySize, DIFF_SMEM);

    prep_kernel<<<PREP_BLOCKS, dim3(16, 16)>>>(L, f, W1, b1);
    u0_kernel<<<NROWS / 16, 256>>>(f, Ws, bs, W2, b2);

    for (int it = 0; it < NITER; it++) {
        int sel = it & 1;
        float* fo = (it == NITER - 1) ? out : nullptr;
        if (it < NFP8)
            diff8_kernel<<<NROWS / 64, 128, DIFF_SMEM>>>(sel, fo);
        else
            diff_kernel<<<NROWS / 64, 128, DIFF_SMEM>>>(sel, fo);
    }
}

// round 13
// speedup vs baseline: 3.1626x; 1.2615x over previous
#include <cuda_runtime.h>
#include <cuda_bf16.h>
#include <cstdint>

#define NROWS 16384
#define INF   512
#define HID   256
#define OUTF  16
#define NITER 16
#define SIGMA2 0.1f
#define L8_SCALE 8192.0f               // L stored as L * 2^13 in e4m3

// ---------------- scratch (static device globals; no allocation) ----------------
__device__ unsigned char g_L8[(size_t)NROWS * NROWS];          // 256 MB e4m3 L * 2^13
__device__ float         g_h [(size_t)NROWS * HID];            // 16 MB hidden
__device__ float         g_u [2][(size_t)NROWS * OUTF];        // fp32 u ping-pong
__device__ unsigned char g_uT8[2][(size_t)OUTF * NROWS];       // e4m3 u^T ping-pong

// ---------------- PTX helpers ----------------
__device__ __forceinline__ uint32_t smem_to_u32(const void* p) {
    uint32_t a;
    asm("{ .reg .u64 t; cvta.to.shared.u64 t, %1; cvt.u32.u64 %0, t; }" : "=r"(a) : "l"(p));
    return a;
}
#define SMEM_SWIZZLE_128B(off) ((off) ^ (((off) >> 3) & 0x70))

__device__ __forceinline__ void cp_async16(uint32_t dst, const void* src) {
    asm volatile("cp.async.cg.shared.global [%0], [%1], 16;" :: "r"(dst), "l"(src) : "memory");
}

#define LDSM_X4(r0_, r1_, r2_, r3_, addr_) \
    asm volatile("ldmatrix.sync.aligned.m8n8.x4.shared.b16 {%0,%1,%2,%3}, [%4];" \
        : "=r"(r0_), "=r"(r1_), "=r"(r2_), "=r"(r3_) : "r"(addr_))

__device__ __forceinline__ void mma16832_e4m3(float* c, uint32_t a0, uint32_t a1, uint32_t a2,
                                              uint32_t a3, uint32_t b0, uint32_t b1) {
    asm volatile(
        "mma.sync.aligned.m16n8k32.row.col.f32.e4m3.e4m3.f32 "
        "{%0,%1,%2,%3}, {%4,%5,%6,%7}, {%8,%9}, {%0,%1,%2,%3};"
        : "+f"(c[0]), "+f"(c[1]), "+f"(c[2]), "+f"(c[3])
        : "r"(a0), "r"(a1), "r"(a2), "r"(a3), "r"(b0), "r"(b1));
}

// pack two floats -> two e4m3 bytes (lo = x, hi = y)
__device__ __forceinline__ uint16_t f2_to_e4m3x2(float x, float y) {
    uint16_t p;
    asm("cvt.rn.satfinite.e4m3x2.f32 %0, %1, %2;" : "=h"(p) : "f"(y), "f"(x));
    return p;
}
__device__ __forceinline__ unsigned char f_to_e4m3(float v) {
    return (unsigned char)(f2_to_e4m3x2(v, 0.f) & 0xFF);
}

// ============================================================================
// prep_kernel: heterogeneous grid fusing two INDEPENDENT jobs.
//   blockIdx.x % 3 == 0  (512 blocks): L fp32 -> e4m3 * 2^13 (fp8 only now)
//   else                 (1024 blocks): one 64x64 tile of h = elu(f@W1 + b1)
// ============================================================================
#define PREP_CONV_BLOCKS 512
#define PREP_HID_BLOCKS  1024
#define PREP_BLOCKS      (PREP_CONV_BLOCKS + PREP_HID_BLOCKS)

__global__ __launch_bounds__(256) void prep_kernel(const float* __restrict__ L,
                                                   const float* __restrict__ f,
                                                   const float* __restrict__ W1,
                                                   const float* __restrict__ b1) {
    __shared__ float As[16][68];
    __shared__ float Bs[16][68];
    int bid = blockIdx.x;

    if (bid % 3 == 0) {
        int conv_id = bid / 3;
        int tid256 = threadIdx.y * 16 + threadIdx.x;
        size_t total8 = (size_t)NROWS * NROWS / 8;   // 8 floats per iter
        size_t stride = (size_t)PREP_CONV_BLOCKS * 256;
        const float4* L4 = (const float4*)L;
        uint2* out8 = (uint2*)g_L8;
        for (size_t i = (size_t)conv_id * 256 + tid256; i < total8; i += stride) {
            float4 v0 = L4[i * 2];
            float4 v1 = L4[i * 2 + 1];
            uint32_t q01 = f2_to_e4m3x2(v0.x * L8_SCALE, v0.y * L8_SCALE)
                         | ((uint32_t)f2_to_e4m3x2(v0.z * L8_SCALE, v0.w * L8_SCALE) << 16);
            uint32_t q23 = f2_to_e4m3x2(v1.x * L8_SCALE, v1.y * L8_SCALE)
                         | ((uint32_t)f2_to_e4m3x2(v1.z * L8_SCALE, v1.w * L8_SCALE) << 16);
            out8[i] = make_uint2(q01, q23);
        }
        return;
    }

    int hid_id = bid - bid / 3 - 1;
    int tx = threadIdx.x, ty = threadIdx.y;
    int tid = ty * 16 + tx;
    int col0 = (hid_id & 3) * 64;
    int row0 = (hid_id >> 2) * 64;
    float acc[4][4] = {};
    for (int k0 = 0; k0 < INF; k0 += 16) {
        #pragma unroll
        for (int it = 0; it < 4; it++) {
            int r  = (tid >> 4) + it * 16;
            int kk = tid & 15;
            As[kk][r] = f[(size_t)(row0 + r) * INF + k0 + kk];
        }
        #pragma unroll
        for (int it = 0; it < 4; it++) {
            int kk = (tid >> 6) + it * 4;
            int c  = tid & 63;
            Bs[kk][c] = W1[(size_t)(k0 + kk) * HID + col0 + c];
        }
        __syncthreads();
        #pragma unroll
        for (int kk = 0; kk < 16; kk++) {
            float4 a4 = *(const float4*)&As[kk][ty * 4];
            float4 b4 = *(const float4*)&Bs[kk][tx * 4];
            float av[4] = {a4.x, a4.y, a4.z, a4.w};
            float bv[4] = {b4.x, b4.y, b4.z, b4.w};
            #pragma unroll
            for (int i = 0; i < 4; i++)
                #pragma unroll
                for (int j = 0; j < 4; j++)
                    acc[i][j] += av[i] * bv[j];
        }
        __syncthreads();
    }
    #pragma unroll
    for (int i = 0; i < 4; i++) {
        int r = row0 + ty * 4 + i;
        #pragma unroll
        for (int j = 0; j < 4; j++) {
            int c = col0 + tx * 4 + j;
            float v = acc[i][j] + b1[c];
            v = v > 0.0f ? v : expm1f(v);
            g_h[(size_t)r * HID + c] = v;
        }
    }
}

// ---------------- u0 = f@Ws + bs + h@W2 + b2 (writes fp32 u + fp8 u^T) ----------------
__global__ __launch_bounds__(256) void u0_kernel(const float* __restrict__ f,
                                                 const float* __restrict__ Ws,
                                                 const float* __restrict__ bs,
                                                 const float* __restrict__ W2,
                                                 const float* __restrict__ b2) {
    __shared__ float sWs[INF * OUTF];
    __shared__ float sW2[HID * OUTF];
    int tid = threadIdx.x;
    for (int i = tid; i < INF * OUTF; i += 256) sWs[i] = Ws[i];
    for (int i = tid; i < HID * OUTF; i += 256) sW2[i] = W2[i];
    __syncthreads();
    int c   = tid & 15;
    int row = blockIdx.x * 16 + (tid >> 4);
    float acc = bs[c] + b2[c];
    const float4* f4 = (const float4*)(f + (size_t)row * INF);
    #pragma unroll 4
    for (int k4 = 0; k4 < INF / 4; k4++) {
        float4 v = f4[k4];
        int k = k4 * 4;
        acc += v.x * sWs[k * 16 + c] + v.y * sWs[(k + 1) * 16 + c]
             + v.z * sWs[(k + 2) * 16 + c] + v.w * sWs[(k + 3) * 16 + c];
    }
    const float4* h4 = (const float4*)(g_h + (size_t)row * HID);
    #pragma unroll 4
    for (int k4 = 0; k4 < HID / 4; k4++) {
        float4 v = h4[k4];
        int k = k4 * 4;
        acc += v.x * sW2[k * 16 + c] + v.y * sW2[(k + 1) * 16 + c]
             + v.z * sW2[(k + 2) * 16 + c] + v.w * sW2[(k + 3) * 16 + c];
    }
    g_u[0][(size_t)row * OUTF + c] = acc;
    g_uT8[0][(size_t)c * NROWS + row] = f_to_e4m3(acc);
}

// ---- pipeline geometry ----
#define NSTG 5
#define A_SUB 8192                     // 64 rows x 128B
#define B_SUB 2048                     // 16 rows x 128B
#define STG_BYTES (2 * A_SUB + 2 * B_SUB)   // 20480
#define DIFF_SMEM (NSTG * STG_BYTES)        // 102400
#define KCH8 256
#define NCHUNK8 (NROWS / KCH8)         // 64

// ============================================================================
// diff8_kernel (e4m3): 256 CTAs x 128 threads, D[64,16] = (L*2^13)[rows,:] @ u.
// 256B contiguous per row per chunk; two 128B SW128 sub-tiles; coalesced
// cp.async (8 lanes cover one row's 128B per instruction); 5-stage
// single-barrier pipeline; 2 CTAs/SM, one wave.
// ============================================================================
__global__ __launch_bounds__(128, 2) void diff8_kernel(int sel_in, float* __restrict__ final_out) {
    extern __shared__ char smem[];
    uint32_t sbase = smem_to_u32(smem);
    int tid = threadIdx.x;
    int wid = tid >> 5, lane = tid & 31;
    int r0 = blockIdx.x * 64;

    const unsigned char* Abase = g_L8 + (size_t)r0 * NROWS;
    const unsigned char* uT    = g_uT8[sel_in];

    const int l_row = tid >> 3;
    const int l_seg = tid & 7;

    auto load_chunk = [&](int j, int s) {
        uint32_t base = sbase + (uint32_t)s * STG_BYTES;
        int k0 = j * KCH8;   // bytes
        #pragma unroll
        for (int i = 0; i < 4; i++) {
            int row = l_row + 16 * i;
            const unsigned char* src = Abase + (size_t)row * NROWS + k0 + l_seg * 16;
            uint32_t off = SMEM_SWIZZLE_128B((uint32_t)(row * 128 + l_seg * 16));
            cp_async16(base + off, src);               // sub-tile 0: k[0..127]
            cp_async16(base + A_SUB + off, src + 128); // sub-tile 1: k[128..255]
        }
        const unsigned char* bsrc = uT + (size_t)l_row * NROWS + k0 + l_seg * 16;
        uint32_t boff = SMEM_SWIZZLE_128B((uint32_t)(l_row * 128 + l_seg * 16));
        cp_async16(base + 2 * A_SUB + boff, bsrc);
        cp_async16(base + 2 * A_SUB + B_SUB + boff, bsrc + 128);
    };

    #pragma unroll
    for (int i = 0; i < NSTG - 1; i++) {
        load_chunk(i, i);
        asm volatile("cp.async.commit_group;" ::: "memory");
    }

    const int a_r = lane & 15;
    const int a_h = (lane >> 4) * 16;
    const int b_n = (lane & 7) + ((lane & 16) ? 8 : 0);
    const int b_h = ((lane >> 3) & 1) * 16;

    float acc0[4] = {0.f, 0.f, 0.f, 0.f};
    float acc1[4] = {0.f, 0.f, 0.f, 0.f};

    for (int i = 0; i < NCHUNK8; i++) {
        int s = i % NSTG;
        asm volatile("cp.async.wait_group %0;" :: "n"(NSTG - 2) : "memory");
        __syncthreads();

        int j = i + NSTG - 1;
        if (j < NCHUNK8) load_chunk(j, j % NSTG);
        asm volatile("cp.async.commit_group;" ::: "memory");

        uint32_t base = sbase + (uint32_t)s * STG_BYTES;
        #pragma unroll
        for (int sub = 0; sub < 2; sub++) {
            uint32_t Ab = base + (uint32_t)sub * A_SUB;
            uint32_t Bb = base + 2 * A_SUB + (uint32_t)sub * B_SUB;
            #pragma unroll
            for (int kk = 0; kk < 64; kk += 16) {     // pseudo-b16 units; 32 real k each
                uint32_t aoff = (uint32_t)((wid * 16 + a_r) * 128 + kk * 2 + a_h);
                uint32_t a0, a1, a2, a3;
                LDSM_X4(a0, a1, a2, a3, Ab + SMEM_SWIZZLE_128B(aoff));
                uint32_t boff = (uint32_t)(b_n * 128 + kk * 2 + b_h);
                uint32_t b0, b1, b2, b3;
                LDSM_X4(b0, b1, b2, b3, Bb + SMEM_SWIZZLE_128B(boff));
                mma16832_e4m3(acc0, a0, a1, a2, a3, b0, b1);
                mma16832_e4m3(acc1, a0, a1, a2, a3, b2, b3);
            }
        }
    }

    // ---- epilogue: u_new = u - (sigma2/2^13) * acc ----
    const float s2 = SIGMA2 / L8_SCALE;
    int gr = lane >> 2;
    int gc = (lane & 3) * 2;
    int rowA = r0 + wid * 16 + gr;
    int rowB = rowA + 8;

    const float* uA = g_u[sel_in] + (size_t)rowA * OUTF;
    const float* uB = g_u[sel_in] + (size_t)rowB * OUTF;
    float rA[4], rB[4];
    rA[0] = uA[gc]     - s2 * acc0[0];
    rA[1] = uA[gc + 1] - s2 * acc0[1];
    rA[2] = uA[gc + 8] - s2 * acc1[0];
    rA[3] = uA[gc + 9] - s2 * acc1[1];
    rB[0] = uB[gc]     - s2 * acc0[2];
    rB[1] = uB[gc + 1] - s2 * acc0[3];
    rB[2] = uB[gc + 8] - s2 * acc1[2];
    rB[3] = uB[gc + 9] - s2 * acc1[3];

    if (final_out) {
        *(float2*)(final_out + (size_t)rowA * OUTF + gc)     = make_float2(rA[0], rA[1]);
        *(float2*)(final_out + (size_t)rowA * OUTF + gc + 8) = make_float2(rA[2], rA[3]);
        *(float2*)(final_out + (size_t)rowB * OUTF + gc)     = make_float2(rB[0], rB[1]);
        *(float2*)(final_out + (size_t)rowB * OUTF + gc + 8) = make_float2(rB[2], rB[3]);
    } else {
        int so = sel_in ^ 1;
        float* uo = g_u[so];
        *(float2*)(uo + (size_t)rowA * OUTF + gc)     = make_float2(rA[0], rA[1]);
        *(float2*)(uo + (size_t)rowA * OUTF + gc + 8) = make_float2(rA[2], rA[3]);
        *(float2*)(uo + (size_t)rowB * OUTF + gc)     = make_float2(rB[0], rB[1]);
        *(float2*)(uo + (size_t)rowB * OUTF + gc + 8) = make_float2(rB[2], rB[3]);
        unsigned char* t8 = g_uT8[so];
        #pragma unroll
        for (int q = 0; q < 4; q++) {
            int cA = (q < 2) ? gc + q : gc + 6 + q;   // gc,gc+1,gc+8,gc+9
            t8[(size_t)cA * NROWS + rowA] = f_to_e4m3(rA[q]);
            t8[(size_t)cA * NROWS + rowB] = f_to_e4m3(rB[q]);
        }
    }
}

// ---------------- launch ----------------
extern "C" void kernel_launch(void* const* d_in, const int* in_sizes, int n_in,
                              void* d_out, int out_size) {
    const float* f  = (const float*)d_in[0];
    const float* L  = (const float*)d_in[1];
    const float* W1 = (const float*)d_in[2];
    const float* b1 = (const float*)d_in[3];
    const float* W2 = (const float*)d_in[4];
    const float* b2 = (const float*)d_in[5];
    const float* Ws = (const float*)d_in[6];
    const float* bs = (const float*)d_in[7];
    float* out = (float*)d_out;
    (void)in_sizes; (void)n_in; (void)out_size;

    cudaFuncSetAttribute(diff8_kernel, cudaFuncAttributeMaxDynamicSharedMemorySize, DIFF_SMEM);

    prep_kernel<<<PREP_BLOCKS, dim3(16, 16)>>>(L, f, W1, b1);
    u0_kernel<<<NROWS / 16, 256>>>(f, Ws, bs, W2, b2);

    for (int it = 0; it < NITER; it++) {
        int sel = it & 1;
        float* fo = (it == NITER - 1) ? out : nullptr;
        diff8_kernel<<<NROWS / 64, 128, DIFF_SMEM>>>(sel, fo);
    }
}